// round 2
// baseline (speedup 1.0000x reference)
#include <cuda_runtime.h>
#include <math.h>

// VectorQuantizer: N=131072 rows of dim 64 vs 512 codes of dim 64.
// Outputs (float32, concatenated per reference tuple order):
//   [0,        8388608)  quantized_st = latents + (codebook[code] - latents)
//   [8388608,  8519680)  codes (as float)
//   [8519680]            commitment*0.25
//   [8519681]            codebook_loss
//   [8519682]            perplexity
//
// CRITICAL: scores replicate the reference fp32 rounding pipeline exactly:
//   x2  = sequential sum_d round(x_d*x_d)            (mul, add separate)
//   mm  = sequential fma chain over d (Eigen gebp)
//   c2  = sequential sum_d round(c_d*c_d)
//   d2  = round( round(x2 - 2*mm) + c2 )
//   argmin = first minimum (strict <)
#define K_CODES 512
#define DIMV 64
#define NROWS 131072
#define TPB 512

__device__ double g_sqsum;
__device__ int g_counts[K_CODES];

__global__ void vq_init_kernel() {
    int t = blockIdx.x * blockDim.x + threadIdx.x;
    if (t == 0) g_sqsum = 0.0;
    if (t < K_CODES) g_counts[t] = 0;
}

__global__ __launch_bounds__(TPB, 1)
void vq_main_kernel(const float* __restrict__ latents,
                    const float* __restrict__ codebook,
                    float* __restrict__ out) {
    extern __shared__ float smem[];
    float* scb   = smem;                        // 512*64 floats (128 KB)
    float* sc2   = smem + K_CODES * DIMV;       // 512 floats
    int*   shist = (int*)(sc2 + K_CODES);       // 512 ints
    float* sred  = (float*)(shist + K_CODES);   // TPB floats

    // Cooperative load of the full codebook into smem (reused by all rows).
    const float4* cb4 = (const float4*)codebook;
    float4* scb4 = (float4*)scb;
    for (int i = threadIdx.x; i < K_CODES * DIMV / 4; i += TPB)
        scb4[i] = cb4[i];
    for (int k = threadIdx.x; k < K_CODES; k += TPB) shist[k] = 0;
    __syncthreads();
    // Per-code squared norms: sequential, separate mul/add roundings
    // (replicates XLA scalar reduce of codebook*codebook).
    for (int k = threadIdx.x; k < K_CODES; k += TPB) {
        float s = 0.f;
        const float* c = scb + k * DIMV;
        #pragma unroll
        for (int d = 0; d < DIMV; ++d) s = __fadd_rn(s, __fmul_rn(c[d], c[d]));
        sc2[k] = s;
    }
    __syncthreads();

    const int row = blockIdx.x * TPB + threadIdx.x;

    // Latent row in registers (16 x float4).
    float4 xv[16];
    const float4* lp = (const float4*)(latents + (size_t)row * DIMV);
    #pragma unroll
    for (int i = 0; i < 16; ++i) xv[i] = lp[i];

    // x2: sequential over d, separate mul/add roundings.
    float x2 = 0.f;
    #pragma unroll
    for (int i = 0; i < 16; ++i) {
        x2 = __fadd_rn(x2, __fmul_rn(xv[i].x, xv[i].x));
        x2 = __fadd_rn(x2, __fmul_rn(xv[i].y, xv[i].y));
        x2 = __fadd_rn(x2, __fmul_rn(xv[i].z, xv[i].z));
        x2 = __fadd_rn(x2, __fmul_rn(xv[i].w, xv[i].w));
    }

    // argmin over rounded reference-style scores. 8 codes in flight for ILP;
    // each code's dot is a strict sequential fp32 FMA chain over d=0..63.
    float best = 3.4e38f;
    int bestk = 0;
    for (int k0 = 0; k0 < K_CODES; k0 += 8) {
        float acc[8];
        #pragma unroll
        for (int j = 0; j < 8; ++j) acc[j] = 0.f;
        #pragma unroll
        for (int dv = 0; dv < 16; ++dv) {
            const float4 xd = xv[dv];
            #pragma unroll
            for (int j = 0; j < 8; ++j) {
                const float4 cd = ((const float4*)(scb + (k0 + j) * DIMV))[dv];
                float a = acc[j];
                a = __fmaf_rn(xd.x, cd.x, a);
                a = __fmaf_rn(xd.y, cd.y, a);
                a = __fmaf_rn(xd.z, cd.z, a);
                a = __fmaf_rn(xd.w, cd.w, a);
                acc[j] = a;
            }
        }
        #pragma unroll
        for (int j = 0; j < 8; ++j) {
            // (x2 - 2*mm) rounds once (2*mm and negation are exact), then +c2 rounds.
            float s = __fadd_rn(__fadd_rn(x2, -2.f * acc[j]), sc2[k0 + j]);
            if (s < best) { best = s; bestk = k0 + j; }  // first-min tie-break
        }
    }

    // Outputs + fused loss partial. Replicate l + (q - l) roundings.
    float* qout = out + (size_t)row * DIMV;
    const float4* cq = (const float4*)(scb + bestk * DIMV);
    float rowsq = 0.f;
    #pragma unroll
    for (int i = 0; i < 16; ++i) {
        float4 q = cq[i];
        float4 l = xv[i];
        float4 o;
        o.x = __fadd_rn(l.x, __fsub_rn(q.x, l.x));
        o.y = __fadd_rn(l.y, __fsub_rn(q.y, l.y));
        o.z = __fadd_rn(l.z, __fsub_rn(q.z, l.z));
        o.w = __fadd_rn(l.w, __fsub_rn(q.w, l.w));
        float dx = l.x - q.x, dy = l.y - q.y, dz = l.z - q.z, dw = l.w - q.w;
        rowsq = fmaf(dx, dx, rowsq);
        rowsq = fmaf(dy, dy, rowsq);
        rowsq = fmaf(dz, dz, rowsq);
        rowsq = fmaf(dw, dw, rowsq);
        ((float4*)qout)[i] = o;
    }
    out[(size_t)NROWS * DIMV + row] = (float)bestk;
    atomicAdd(&shist[bestk], 1);

    // Block reduce the squared-diff sum, one double atomic per block.
    sred[threadIdx.x] = rowsq;
    __syncthreads();
    for (int s = TPB / 2; s > 0; s >>= 1) {
        if (threadIdx.x < s) sred[threadIdx.x] += sred[threadIdx.x + s];
        __syncthreads();
    }
    if (threadIdx.x == 0) atomicAdd(&g_sqsum, (double)sred[0]);
    // Flush smem histogram to global.
    for (int k = threadIdx.x; k < K_CODES; k += TPB) {
        int c = shist[k];
        if (c) atomicAdd(&g_counts[k], c);
    }
}

__global__ void vq_finalize_kernel(float* __restrict__ out) {
    __shared__ float red[K_CODES];
    int t = threadIdx.x;
    float p = (float)g_counts[t] / (float)NROWS;
    red[t] = -p * logf(p + 1e-10f);
    __syncthreads();
    for (int s = K_CODES / 2; s > 0; s >>= 1) {
        if (t < s) red[t] += red[t + s];
        __syncthreads();
    }
    if (t == 0) {
        float perp = expf(red[0]);
        float msd = (float)(g_sqsum / (double)((size_t)NROWS * DIMV));
        size_t base = (size_t)NROWS * DIMV + NROWS;
        out[base + 0] = msd * 0.25f;   // commitment * COMMITMENT_COST
        out[base + 1] = msd;           // codebook loss
        out[base + 2] = perp;          // perplexity
    }
}

extern "C" void kernel_launch(void* const* d_in, const int* in_sizes, int n_in,
                              void* d_out, int out_size) {
    (void)in_sizes; (void)n_in; (void)out_size;
    const float* latents  = (const float*)d_in[0];
    const float* codebook = (const float*)d_in[1];
    float* out = (float*)d_out;

    const int smem_bytes = (K_CODES * DIMV) * 4   // codebook
                         + K_CODES * 4            // c2
                         + K_CODES * 4            // hist
                         + TPB * 4;               // reduce
    cudaFuncSetAttribute(vq_main_kernel,
                         cudaFuncAttributeMaxDynamicSharedMemorySize, smem_bytes);

    vq_init_kernel<<<2, 256>>>();
    vq_main_kernel<<<NROWS / TPB, TPB, smem_bytes>>>(latents, codebook, out);
    vq_finalize_kernel<<<1, K_CODES>>>(out);
}